// round 3
// baseline (speedup 1.0000x reference)
#include <cuda_runtime.h>
#include <cstdint>

// ---------------------------------------------------------------------------
// Problem constants
// ---------------------------------------------------------------------------
#define NB    4096      // batch
#define DIN   2048
#define HH    1024
#define DD    256       // latent dim == HW
#define NSTEP 15
#define S     16        // samples per trace CTA

// ---------------------------------------------------------------------------
// Scratch (device globals; no allocation allowed)
// ---------------------------------------------------------------------------
__device__ float g_H   [2 * NB * HH];   // 32 MB  tanh(x@W1+b1) for start|end
__device__ float g_Z   [2 * NB * DD];   //  8 MB  z_s rows 0..4095, z_e rows 4096..8191
__device__ float g_HW  [NB * DD];       //  4 MB  tanh(z_s@Ww1+bw1)
__device__ float g_V   [NB * DD];       //  4 MB  W_start
__device__ float g_WpT [DD * DD];       // Wp1 transposed
__device__ float g_mind[NB];            // per-sample min dist^2

// ---------------------------------------------------------------------------
// Packed fp32x2 helpers (FFMA2 — only reachable via PTX)
// ---------------------------------------------------------------------------
__device__ __forceinline__ unsigned long long pack2(float x, float y) {
    unsigned long long r;
    asm("mov.b64 %0, {%1, %2};" : "=l"(r) : "f"(x), "f"(y));
    return r;
}
__device__ __forceinline__ float2 unpack2(unsigned long long v) {
    float2 r;
    asm("mov.b64 {%0, %1}, %2;" : "=f"(r.x), "=f"(r.y) : "l"(v));
    return r;
}
__device__ __forceinline__ unsigned long long fma2(unsigned long long a,
                                                   unsigned long long b,
                                                   unsigned long long c) {
    unsigned long long d;
    asm("fma.rn.f32x2 %0, %1, %2, %3;" : "=l"(d) : "l"(a), "l"(b), "l"(c));
    return d;
}

// ---------------------------------------------------------------------------
// Generic SGEMM: C[M,N] = act(A[M,K] @ B[K,N] + bias[N]), row-major.
// BM=BN=128, BK=8, 256 threads, 8x8 per thread, f32x2 accumulators.
// Requires M%128==0, N%128==0, K%8==0 (true for all our shapes).
// ---------------------------------------------------------------------------
template <int ACT>
__global__ __launch_bounds__(256)
void sgemm_kernel(const float* __restrict__ A, const float* __restrict__ Bm,
                  const float* __restrict__ bias, float* __restrict__ C,
                  int M, int N, int K) {
    __shared__ __align__(16) float As[8][128];
    __shared__ __align__(16) float Bs[8][128];

    const int tid  = threadIdx.x;
    const int brow = blockIdx.y * 128;
    const int bcol = blockIdx.x * 128;
    const int ty   = tid >> 4;          // 0..15
    const int tx   = tid & 15;          // 0..15

    const int arow  = tid >> 1;          // 0..127
    const int acol  = (tid & 1) * 4;     // 0 or 4
    const int browB = tid >> 5;          // 0..7
    const int bcolB = (tid & 31) * 4;    // 0..124

    const float* Aptr = A  + (size_t)(brow + arow) * K + acol;
    const float* Bptr = Bm + (size_t)browB * N + bcol + bcolB;

    unsigned long long c2[8][4];
#pragma unroll
    for (int m = 0; m < 8; m++)
#pragma unroll
        for (int j = 0; j < 4; j++) c2[m][j] = 0ull;

    for (int k0 = 0; k0 < K; k0 += 8) {
        float4 av = *(const float4*)(Aptr + k0);
        float4 bv = *(const float4*)(Bptr + (size_t)k0 * N);
        As[acol + 0][arow] = av.x;
        As[acol + 1][arow] = av.y;
        As[acol + 2][arow] = av.z;
        As[acol + 3][arow] = av.w;
        *(float4*)&Bs[browB][bcolB] = bv;
        __syncthreads();

#pragma unroll
        for (int kk = 0; kk < 8; kk++) {
            float4 a0 = *(const float4*)&As[kk][ty * 8];
            float4 a1 = *(const float4*)&As[kk][ty * 8 + 4];
            const unsigned long long* br = (const unsigned long long*)&Bs[kk][tx * 8];
            unsigned long long b2[4];
#pragma unroll
            for (int j = 0; j < 4; j++) b2[j] = br[j];
            float am[8] = {a0.x, a0.y, a0.z, a0.w, a1.x, a1.y, a1.z, a1.w};
#pragma unroll
            for (int m = 0; m < 8; m++) {
                unsigned long long a2 = pack2(am[m], am[m]);
#pragma unroll
                for (int j = 0; j < 4; j++) c2[m][j] = fma2(a2, b2[j], c2[m][j]);
            }
        }
        __syncthreads();
    }

#pragma unroll
    for (int m = 0; m < 8; m++) {
        const int row = brow + ty * 8 + m;
        float* crow = C + (size_t)row * N + bcol + tx * 8;
#pragma unroll
        for (int j = 0; j < 4; j++) {
            float2 p = unpack2(c2[m][j]);
            const int n = bcol + tx * 8 + 2 * j;
            p.x += bias[n];
            p.y += bias[n + 1];
            if (ACT) { p.x = tanhf(p.x); p.y = tanhf(p.y); }
            *(float2*)&crow[2 * j] = p;
        }
    }
}

// ---------------------------------------------------------------------------
// Wp1 transpose (tiny: 256x256)
// ---------------------------------------------------------------------------
__global__ void transpose256(const float* __restrict__ in, float* __restrict__ out) {
    int i = blockIdx.x, j = threadIdx.x;
    out[j * DD + i] = in[i * DD + j];
}

// ---------------------------------------------------------------------------
// Degenerate-wind fallback:  V += noise/(||noise||+1e-12)*1e-4  iff ||V|| < 1e-5
// ---------------------------------------------------------------------------
__global__ void fallback_kernel(float* __restrict__ V, const float* __restrict__ noise) {
    __shared__ float rw[8], rn[8];
    const int s = blockIdx.x, t = threadIdx.x;
    const int lane = t & 31, warp = t >> 5;
    float w = V[s * DD + t];
    float n = noise[s * DD + t];
    float pw = w * w, pn = n * n;
#pragma unroll
    for (int off = 16; off > 0; off >>= 1) {
        pw += __shfl_xor_sync(0xffffffffu, pw, off);
        pn += __shfl_xor_sync(0xffffffffu, pn, off);
    }
    if (lane == 0) { rw[warp] = pw; rn[warp] = pn; }
    __syncthreads();
    float sw = 0.f, sn = 0.f;
#pragma unroll
    for (int i = 0; i < 8; i++) { sw += rw[i]; sn += rn[i]; }
    float wn = sqrtf(sw + 1e-24f);
    if (wn < 1e-5f) {
        float nn = sqrtf(sn + 1e-24f);
        V[s * DD + t] = w + n / (nn + 1e-12f) * 1e-4f;
    }
}

// ---------------------------------------------------------------------------
// Trace kernel: 16 samples per CTA, 256 threads (thread = dim index).
// State in registers; xt / scaled-tanh vectors through smem (transposed
// [dim][sample] layout, broadcast ulonglong2 LDS, f32x2 FMAs).
// ---------------------------------------------------------------------------
__global__ __launch_bounds__(256, 2)
void trace_kernel(const float* __restrict__ Z,    // [8192,256]: z_s | z_e
                  const float* __restrict__ V,    // [4096,256]
                  const float* __restrict__ Wp1,  // [256,256]
                  const float* __restrict__ WpT,  // transposed
                  const float* __restrict__ bp1,
                  const float* __restrict__ wp2,
                  float* __restrict__ mind) {
    __shared__ __align__(16) float xt_sm[DD * S];
    __shared__ __align__(16) float sv_sm[DD * S];
    __shared__ float red_a[8 * S];
    __shared__ float red_b[8 * S];
    __shared__ float bc_a[S];
    __shared__ float bc_b[S];

    const int t    = threadIdx.x;
    const int lane = t & 31;
    const int warp = t >> 5;
    const int s0   = blockIdx.x * S;
    const float hstep = 1.0f / 15.0f;
    const float bp = bp1[t];
    const float w2 = wp2[t];

    float x[S], v[S], vt[S], g[S], xacc[S], vacc[S];
#pragma unroll
    for (int s = 0; s < S; s++) {
        x[s] = Z[(size_t)(s0 + s) * DD + t];
        v[s] = V[(size_t)(s0 + s) * DD + t];
    }
    float mymin = 3.4e38f;

    // accel: inputs = xt (already in xt_sm), vt (regs) ; output -> g (regs)
#define ACCEL()                                                                \
    do {                                                                       \
        __syncthreads(); /* xt published */                                    \
        {                                                                      \
            unsigned long long hacc[S / 2];                                    \
            _Pragma("unroll") for (int k = 0; k < S / 2; k++) hacc[k] = 0ull;  \
            _Pragma("unroll 2") for (int i = 0; i < DD; i++) {                 \
                float w = Wp1[i * DD + t];                                     \
                unsigned long long wp = pack2(w, w);                           \
                const ulonglong2* xr = (const ulonglong2*)(xt_sm + i * S);     \
                _Pragma("unroll") for (int k = 0; k < S / 4; k++) {            \
                    ulonglong2 xv = xr[k];                                     \
                    hacc[2 * k]     = fma2(wp, xv.x, hacc[2 * k]);             \
                    hacc[2 * k + 1] = fma2(wp, xv.y, hacc[2 * k + 1]);         \
                }                                                              \
            }                                                                  \
            _Pragma("unroll") for (int k = 0; k < S / 2; k++) {                \
                float2 p = unpack2(hacc[k]);                                   \
                float h0 = tanhf(p.x + bp);                                    \
                float h1 = tanhf(p.y + bp);                                    \
                float2 ssv;                                                    \
                ssv.x = (1.0f - h0 * h0) * w2;                                 \
                ssv.y = (1.0f - h1 * h1) * w2;                                 \
                *(float2*)(sv_sm + t * S + 2 * k) = ssv;                       \
            }                                                                  \
        }                                                                      \
        __syncthreads(); /* sv published */                                    \
        {                                                                      \
            unsigned long long gacc[S / 2];                                    \
            _Pragma("unroll") for (int k = 0; k < S / 2; k++) gacc[k] = 0ull;  \
            _Pragma("unroll 2") for (int j = 0; j < DD; j++) {                 \
                float w = WpT[j * DD + t];                                     \
                unsigned long long wp = pack2(w, w);                           \
                const ulonglong2* sr = (const ulonglong2*)(sv_sm + j * S);     \
                _Pragma("unroll") for (int k = 0; k < S / 4; k++) {            \
                    ulonglong2 sv4 = sr[k];                                    \
                    gacc[2 * k]     = fma2(wp, sv4.x, gacc[2 * k]);            \
                    gacc[2 * k + 1] = fma2(wp, sv4.y, gacc[2 * k + 1]);        \
                }                                                              \
            }                                                                  \
            _Pragma("unroll") for (int k = 0; k < S / 2; k++) {                \
                float2 p = unpack2(gacc[k]);                                   \
                g[2 * k] = p.x;                                                \
                g[2 * k + 1] = p.y;                                            \
            }                                                                  \
        }                                                                      \
        _Pragma("unroll") for (int s = 0; s < S; s++) {                        \
            float pg = g[s] * vt[s];                                           \
            float pv = vt[s] * vt[s];                                          \
            _Pragma("unroll") for (int off = 16; off > 0; off >>= 1) {         \
                pg += __shfl_xor_sync(0xffffffffu, pg, off);                   \
                pv += __shfl_xor_sync(0xffffffffu, pv, off);                   \
            }                                                                  \
            if (lane == 0) {                                                   \
                red_a[warp * S + s] = pg;                                      \
                red_b[warp * S + s] = pv;                                      \
            }                                                                  \
        }                                                                      \
        __syncthreads();                                                       \
        if (t < S) {                                                           \
            float sg = 0.f, sv2 = 0.f;                                         \
            _Pragma("unroll") for (int w8 = 0; w8 < 8; w8++) {                 \
                sg += red_a[w8 * S + t];                                       \
                sv2 += red_b[w8 * S + t];                                      \
            }                                                                  \
            bc_a[t] = sg;                                                      \
            bc_b[t] = sv2;                                                     \
        }                                                                      \
        __syncthreads();                                                       \
        _Pragma("unroll") for (int s = 0; s < S; s++) {                        \
            g[s] = 0.5f * bc_b[s] * g[s] - bc_a[s] * vt[s];                    \
        }                                                                      \
    } while (0)

    for (int step = 0; step < NSTEP; step++) {
        // ---- stage 1: a1 = acc(x, v)
#pragma unroll
        for (int s = 0; s < S; s++) {
            xt_sm[t * S + s] = x[s];
            vt[s] = v[s];
        }
        ACCEL();
#pragma unroll
        for (int s = 0; s < S; s++) { xacc[s] = v[s]; vacc[s] = g[s]; }

        // ---- stage 2: a2 = acc(x + h/2 v, v + h/2 a1)
#pragma unroll
        for (int s = 0; s < S; s++) {
            xt_sm[t * S + s] = x[s] + 0.5f * hstep * v[s];
            vt[s] = v[s] + 0.5f * hstep * g[s];
        }
        ACCEL();
#pragma unroll
        for (int s = 0; s < S; s++) { xacc[s] += 2.0f * vt[s]; vacc[s] += 2.0f * g[s]; }

        // ---- stage 3: a3 = acc(x + h/2 k2x, v + h/2 a2)   (k2x = current vt)
#pragma unroll
        for (int s = 0; s < S; s++) {
            float k2x = vt[s];
            xt_sm[t * S + s] = x[s] + 0.5f * hstep * k2x;
            vt[s] = v[s] + 0.5f * hstep * g[s];
        }
        ACCEL();
#pragma unroll
        for (int s = 0; s < S; s++) { xacc[s] += 2.0f * vt[s]; vacc[s] += 2.0f * g[s]; }

        // ---- stage 4: a4 = acc(x + h k3x, v + h a3)   (k3x = current vt)
#pragma unroll
        for (int s = 0; s < S; s++) {
            float k3x = vt[s];
            xt_sm[t * S + s] = x[s] + hstep * k3x;
            vt[s] = v[s] + hstep * g[s];
        }
        ACCEL();
#pragma unroll
        for (int s = 0; s < S; s++) {
            xacc[s] += vt[s];
            vacc[s] += g[s];
            x[s] += (hstep / 6.0f) * xacc[s];
            v[s] += (hstep / 6.0f) * vacc[s];
        }

        // ---- distance to z_e, track min
#pragma unroll
        for (int s = 0; s < S; s++) {
            float dd = x[s] - Z[(size_t)(NB + s0 + s) * DD + t];
            float p = dd * dd;
#pragma unroll
            for (int off = 16; off > 0; off >>= 1)
                p += __shfl_xor_sync(0xffffffffu, p, off);
            if (lane == 0) red_a[warp * S + s] = p;
        }
        __syncthreads();
        if (t < S) {
            float tot = 0.f;
#pragma unroll
            for (int w8 = 0; w8 < 8; w8++) tot += red_a[w8 * S + t];
            mymin = fminf(mymin, tot);
        }
        __syncthreads();
    }

    if (t < S) mind[s0 + t] = mymin;
#undef ACCEL
}

// ---------------------------------------------------------------------------
// Deterministic final reduction: out = mean(mind) * WEIGHT
// ---------------------------------------------------------------------------
__global__ void reduce_kernel(const float* __restrict__ mind, float* __restrict__ out) {
    __shared__ float sm[1024];
    const int t = threadIdx.x;
    float a = mind[t] + mind[t + 1024] + mind[t + 2048] + mind[t + 3072];
    sm[t] = a;
    __syncthreads();
    for (int off = 512; off > 0; off >>= 1) {
        if (t < off) sm[t] += sm[t + off];
        __syncthreads();
    }
    if (t == 0) out[0] = sm[0] * (1.0f / (float)NB);
}

// ---------------------------------------------------------------------------
// Launch
// ---------------------------------------------------------------------------
extern "C" void kernel_launch(void* const* d_in, const int* in_sizes, int n_in,
                              void* d_out, int out_size) {
    const float* x_start = (const float*)d_in[0];
    const float* x_end   = (const float*)d_in[1];
    const float* noise   = (const float*)d_in[2];
    const float* W1  = (const float*)d_in[3];
    const float* b1  = (const float*)d_in[4];
    const float* W2  = (const float*)d_in[5];
    const float* b2  = (const float*)d_in[6];
    const float* Ww1 = (const float*)d_in[7];
    const float* bw1 = (const float*)d_in[8];
    const float* Ww2 = (const float*)d_in[9];
    const float* bw2 = (const float*)d_in[10];
    const float* Wp1 = (const float*)d_in[11];
    const float* bp1 = (const float*)d_in[12];
    const float* wp2 = (const float*)d_in[13];

    float *Hb, *Zb, *HWb, *Vb, *WpT, *Md;
    cudaGetSymbolAddress((void**)&Hb,  g_H);
    cudaGetSymbolAddress((void**)&Zb,  g_Z);
    cudaGetSymbolAddress((void**)&HWb, g_HW);
    cudaGetSymbolAddress((void**)&Vb,  g_V);
    cudaGetSymbolAddress((void**)&WpT, g_WpT);
    cudaGetSymbolAddress((void**)&Md,  g_mind);

    // Wp1 transpose for the backward matvec
    transpose256<<<DD, DD>>>(Wp1, WpT);

    // Encoder layer 1: H = tanh(X @ W1 + b1)   (start, end)
    sgemm_kernel<1><<<dim3(HH / 128, NB / 128), 256>>>(x_start, W1, b1, Hb, NB, HH, DIN);
    sgemm_kernel<1><<<dim3(HH / 128, NB / 128), 256>>>(x_end,   W1, b1, Hb + (size_t)NB * HH, NB, HH, DIN);
    // Encoder layer 2: Z = H @ W2 + b2   (both halves at once)
    sgemm_kernel<0><<<dim3(DD / 128, 2 * NB / 128), 256>>>(Hb, W2, b2, Zb, 2 * NB, DD, HH);
    // Wind field on z_s
    sgemm_kernel<1><<<dim3(DD / 128, NB / 128), 256>>>(Zb,  Ww1, bw1, HWb, NB, DD, DD);
    sgemm_kernel<0><<<dim3(DD / 128, NB / 128), 256>>>(HWb, Ww2, bw2, Vb,  NB, DD, DD);
    // Degenerate-wind fallback
    fallback_kernel<<<NB, DD>>>(Vb, noise);
    // RK4 geodesic trace + per-sample min distance
    trace_kernel<<<NB / S, DD>>>(Zb, Vb, Wp1, WpT, bp1, wp2, Md);
    // Mean
    reduce_kernel<<<1, 1024>>>(Md, (float*)d_out);
}

// round 4
// speedup vs baseline: 1.2135x; 1.2135x over previous
#include <cuda_runtime.h>
#include <cstdint>

// ---------------------------------------------------------------------------
// Problem constants
// ---------------------------------------------------------------------------
#define NB    4096      // batch
#define DIN   2048
#define HH    1024
#define DD    256       // latent dim == HW
#define NSTEP 15
#define S     16        // samples per trace CTA

// ---------------------------------------------------------------------------
// Scratch (device globals; no allocation allowed)
// ---------------------------------------------------------------------------
__device__ float g_H   [2 * NB * HH];   // 32 MB  tanh(x@W1+b1) for start|end
__device__ float g_Z   [2 * NB * DD];   //  8 MB  z_s rows 0..4095, z_e rows 4096..8191
__device__ float g_HW  [NB * DD];       //  4 MB  tanh(z_s@Ww1+bw1)
__device__ float g_V   [NB * DD];       //  4 MB  W_start
__device__ float g_WpT [DD * DD];       // Wp1 transposed
__device__ float g_mind[NB];            // per-sample min dist^2

// ---------------------------------------------------------------------------
// Packed fp32x2 helpers (FFMA2 — only reachable via PTX)
// ---------------------------------------------------------------------------
__device__ __forceinline__ unsigned long long pack2(float x, float y) {
    unsigned long long r;
    asm("mov.b64 %0, {%1, %2};" : "=l"(r) : "f"(x), "f"(y));
    return r;
}
__device__ __forceinline__ float2 unpack2(unsigned long long v) {
    float2 r;
    asm("mov.b64 {%0, %1}, %2;" : "=f"(r.x), "=f"(r.y) : "l"(v));
    return r;
}
__device__ __forceinline__ unsigned long long fma2(unsigned long long a,
                                                   unsigned long long b,
                                                   unsigned long long c) {
    unsigned long long d;
    asm("fma.rn.f32x2 %0, %1, %2, %3;" : "=l"(d) : "l"(a), "l"(b), "l"(c));
    return d;
}

// ---------------------------------------------------------------------------
// SGEMM v2: C[M,N] = act(A[M,K] @ B[K,N] + bias[N]), row-major.
// BM=BN=128, BK=16, 256 threads, 8x8 per thread, f32x2 accumulators,
// double-buffered smem (one __syncthreads per k-block).
// Requires M%128==0, N%128==0, K%16==0 (true for all our shapes).
// ---------------------------------------------------------------------------
#define ASTRIDE 132   // padded row stride (floats) for As; 132*4=528, 16B aligned

template <int ACT>
__global__ __launch_bounds__(256)
void sgemm_kernel(const float* __restrict__ A, const float* __restrict__ Bm,
                  const float* __restrict__ bias, float* __restrict__ C,
                  int M, int N, int K) {
    __shared__ __align__(16) float As[2 * 16 * ASTRIDE];
    __shared__ __align__(16) float Bs[2 * 16 * 128];

    const int tid  = threadIdx.x;
    const int brow = blockIdx.y * 128;
    const int bcol = blockIdx.x * 128;
    const int ty   = tid >> 4;          // 0..15
    const int tx   = tid & 15;          // 0..15

    // A staging: thread loads 8 consecutive floats of one row
    const int arow = tid >> 1;           // 0..127
    const int acol = (tid & 1) * 8;      // 0 or 8
    // B staging: thread loads 2x float4 (rows r, r+8)
    const int br0  = tid >> 5;           // 0..7
    const int bcl  = (tid & 31) * 4;     // 0..124

    const float* Aptr = A  + (size_t)(brow + arow) * K + acol;
    const float* Bptr = Bm + (size_t)br0 * N + bcol + bcl;

    unsigned long long c2[8][4];
#pragma unroll
    for (int m = 0; m < 8; m++)
#pragma unroll
        for (int j = 0; j < 4; j++) c2[m][j] = 0ull;

    float4 a_rg0, a_rg1, b_rg0, b_rg1;

    // prologue: load tile 0
    a_rg0 = *(const float4*)(Aptr + 0);
    a_rg1 = *(const float4*)(Aptr + 4);
    b_rg0 = *(const float4*)(Bptr);
    b_rg1 = *(const float4*)(Bptr + (size_t)8 * N);
    {
        float am[8] = {a_rg0.x, a_rg0.y, a_rg0.z, a_rg0.w,
                       a_rg1.x, a_rg1.y, a_rg1.z, a_rg1.w};
#pragma unroll
        for (int c = 0; c < 8; c++) As[(acol + c) * ASTRIDE + arow] = am[c];
        *(float4*)&Bs[br0 * 128 + bcl]       = b_rg0;
        *(float4*)&Bs[(br0 + 8) * 128 + bcl] = b_rg1;
    }
    __syncthreads();

    int buf = 0;
    const int nblk = K / 16;
    for (int kb = 0; kb < nblk; kb++) {
        const bool has_next = (kb + 1 < nblk);
        if (has_next) {
            const int k0 = (kb + 1) * 16;
            a_rg0 = *(const float4*)(Aptr + k0);
            a_rg1 = *(const float4*)(Aptr + k0 + 4);
            b_rg0 = *(const float4*)(Bptr + (size_t)k0 * N);
            b_rg1 = *(const float4*)(Bptr + (size_t)(k0 + 8) * N);
        }

        const float* Asb = As + buf * 16 * ASTRIDE;
        const float* Bsb = Bs + buf * 16 * 128;
#pragma unroll
        for (int kk = 0; kk < 16; kk++) {
            float4 a0 = *(const float4*)&Asb[kk * ASTRIDE + ty * 8];
            float4 a1 = *(const float4*)&Asb[kk * ASTRIDE + ty * 8 + 4];
            const unsigned long long* brow2 =
                (const unsigned long long*)&Bsb[kk * 128 + tx * 8];
            unsigned long long b2[4];
#pragma unroll
            for (int j = 0; j < 4; j++) b2[j] = brow2[j];
            float am[8] = {a0.x, a0.y, a0.z, a0.w, a1.x, a1.y, a1.z, a1.w};
#pragma unroll
            for (int m = 0; m < 8; m++) {
                unsigned long long aa = pack2(am[m], am[m]);
#pragma unroll
                for (int j = 0; j < 4; j++) c2[m][j] = fma2(aa, b2[j], c2[m][j]);
            }
        }

        if (has_next) {
            float* Asn = As + (buf ^ 1) * 16 * ASTRIDE;
            float* Bsn = Bs + (buf ^ 1) * 16 * 128;
            float am[8] = {a_rg0.x, a_rg0.y, a_rg0.z, a_rg0.w,
                           a_rg1.x, a_rg1.y, a_rg1.z, a_rg1.w};
#pragma unroll
            for (int c = 0; c < 8; c++) Asn[(acol + c) * ASTRIDE + arow] = am[c];
            *(float4*)&Bsn[br0 * 128 + bcl]       = b_rg0;
            *(float4*)&Bsn[(br0 + 8) * 128 + bcl] = b_rg1;
            __syncthreads();
            buf ^= 1;
        }
    }

#pragma unroll
    for (int m = 0; m < 8; m++) {
        const int row = brow + ty * 8 + m;
        float* crow = C + (size_t)row * N + bcol + tx * 8;
#pragma unroll
        for (int j = 0; j < 4; j++) {
            float2 p = unpack2(c2[m][j]);
            const int n = bcol + tx * 8 + 2 * j;
            p.x += bias[n];
            p.y += bias[n + 1];
            if (ACT) { p.x = tanhf(p.x); p.y = tanhf(p.y); }
            *(float2*)&crow[2 * j] = p;
        }
    }
}

// ---------------------------------------------------------------------------
// Wp1 transpose (tiny: 256x256)
// ---------------------------------------------------------------------------
__global__ void transpose256(const float* __restrict__ in, float* __restrict__ out) {
    int i = blockIdx.x, j = threadIdx.x;
    out[j * DD + i] = in[i * DD + j];
}

// ---------------------------------------------------------------------------
// Degenerate-wind fallback:  V += noise/(||noise||+1e-12)*1e-4  iff ||V|| < 1e-5
// ---------------------------------------------------------------------------
__global__ void fallback_kernel(float* __restrict__ V, const float* __restrict__ noise) {
    __shared__ float rw[8], rn[8];
    const int s = blockIdx.x, t = threadIdx.x;
    const int lane = t & 31, warp = t >> 5;
    float w = V[s * DD + t];
    float n = noise[s * DD + t];
    float pw = w * w, pn = n * n;
#pragma unroll
    for (int off = 16; off > 0; off >>= 1) {
        pw += __shfl_xor_sync(0xffffffffu, pw, off);
        pn += __shfl_xor_sync(0xffffffffu, pn, off);
    }
    if (lane == 0) { rw[warp] = pw; rn[warp] = pn; }
    __syncthreads();
    float sw = 0.f, sn = 0.f;
#pragma unroll
    for (int i = 0; i < 8; i++) { sw += rw[i]; sn += rn[i]; }
    float wn = sqrtf(sw + 1e-24f);
    if (wn < 1e-5f) {
        float nn = sqrtf(sn + 1e-24f);
        V[s * DD + t] = w + n / (nn + 1e-12f) * 1e-4f;
    }
}

// ---------------------------------------------------------------------------
// Trace kernel: 16 samples per CTA, 256 threads (thread = dim index).
// Matvecs use register double-buffered weight columns (8 LDGs in flight,
// prefetched one block ahead) so the L2 latency (~250 cyc) is hidden behind
// 64 FFMA2 per block. Stage vectors go through smem transposed [dim][sample]
// and are read back as broadcast ulonglong2 LDS.
// ---------------------------------------------------------------------------
__global__ __launch_bounds__(256, 2)
void trace_kernel(const float* __restrict__ Z,    // [8192,256]: z_s | z_e
                  const float* __restrict__ V,    // [4096,256]
                  const float* __restrict__ Wp1,  // [256,256]
                  const float* __restrict__ WpT,  // transposed
                  const float* __restrict__ bp1,
                  const float* __restrict__ wp2,
                  float* __restrict__ mind) {
    __shared__ __align__(16) float xt_sm[DD * S];
    __shared__ __align__(16) float sv_sm[DD * S];
    __shared__ float red_a[8 * S];
    __shared__ float red_b[8 * S];
    __shared__ float bc_a[S];
    __shared__ float bc_b[S];

    const int t    = threadIdx.x;
    const int lane = t & 31;
    const int warp = t >> 5;
    const int s0   = blockIdx.x * S;
    const float hstep = 1.0f / 15.0f;
    const float bp = bp1[t];
    const float w2 = wp2[t];

    float x[S], v[S], vt[S], g[S], xacc[S], vacc[S];
#pragma unroll
    for (int s = 0; s < S; s++) {
        x[s] = Z[(size_t)(s0 + s) * DD + t];
        v[s] = V[(size_t)(s0 + s) * DD + t];
    }
    float mymin = 3.4e38f;

    // matvec: acc2[k] (S/2 f32x2) += sum_i W[i][t] * SRC[i][2k..2k+1]
    // weight column register-double-buffered in blocks of 8 rows.
#define MATVEC(WBASE, SRC, ACC2)                                               \
    do {                                                                       \
        const float* Wcol = (WBASE) + t;                                       \
        float wc[8], wn[8];                                                    \
        _Pragma("unroll") for (int u = 0; u < 8; u++) wc[u] = Wcol[u * DD];    \
        _Pragma("unroll") for (int k = 0; k < S / 2; k++) ACC2[k] = 0ull;      \
        _Pragma("unroll 1") for (int ii = 0; ii < DD; ii += 8) {               \
            if (ii + 8 < DD) {                                                 \
                _Pragma("unroll") for (int u = 0; u < 8; u++)                  \
                    wn[u] = Wcol[(ii + 8 + u) * DD];                           \
            }                                                                  \
            _Pragma("unroll") for (int u = 0; u < 8; u++) {                    \
                unsigned long long wp = pack2(wc[u], wc[u]);                   \
                const ulonglong2* xr = (const ulonglong2*)((SRC) + (ii + u) * S); \
                _Pragma("unroll") for (int k = 0; k < S / 4; k++) {            \
                    ulonglong2 xv = xr[k];                                     \
                    ACC2[2 * k]     = fma2(wp, xv.x, ACC2[2 * k]);             \
                    ACC2[2 * k + 1] = fma2(wp, xv.y, ACC2[2 * k + 1]);         \
                }                                                              \
            }                                                                  \
            _Pragma("unroll") for (int u = 0; u < 8; u++) wc[u] = wn[u];       \
        }                                                                      \
    } while (0)

    // accel: inputs = xt (already in xt_sm), vt (regs) ; output -> g (regs)
#define ACCEL()                                                                \
    do {                                                                       \
        __syncthreads(); /* xt published */                                    \
        {                                                                      \
            unsigned long long acc2[S / 2];                                    \
            MATVEC(Wp1, xt_sm, acc2);                                          \
            _Pragma("unroll") for (int k = 0; k < S / 2; k++) {                \
                float2 p = unpack2(acc2[k]);                                   \
                float h0 = tanhf(p.x + bp);                                    \
                float h1 = tanhf(p.y + bp);                                    \
                float2 ssv;                                                    \
                ssv.x = (1.0f - h0 * h0) * w2;                                 \
                ssv.y = (1.0f - h1 * h1) * w2;                                 \
                *(float2*)(sv_sm + t * S + 2 * k) = ssv;                       \
            }                                                                  \
        }                                                                      \
        __syncthreads(); /* sv published */                                    \
        {                                                                      \
            unsigned long long acc2[S / 2];                                    \
            MATVEC(WpT, sv_sm, acc2);                                          \
            _Pragma("unroll") for (int k = 0; k < S / 2; k++) {                \
                float2 p = unpack2(acc2[k]);                                   \
                g[2 * k]     = p.x;                                            \
                g[2 * k + 1] = p.y;                                            \
            }                                                                  \
        }                                                                      \
        _Pragma("unroll") for (int s = 0; s < S; s++) {                        \
            float pg = g[s] * vt[s];                                           \
            float pv = vt[s] * vt[s];                                          \
            _Pragma("unroll") for (int off = 16; off > 0; off >>= 1) {         \
                pg += __shfl_xor_sync(0xffffffffu, pg, off);                   \
                pv += __shfl_xor_sync(0xffffffffu, pv, off);                   \
            }                                                                  \
            if (lane == 0) {                                                   \
                red_a[warp * S + s] = pg;                                      \
                red_b[warp * S + s] = pv;                                      \
            }                                                                  \
        }                                                                      \
        __syncthreads();                                                       \
        if (t < S) {                                                           \
            float sg = 0.f, sv2 = 0.f;                                         \
            _Pragma("unroll") for (int w8 = 0; w8 < 8; w8++) {                 \
                sg += red_a[w8 * S + t];                                       \
                sv2 += red_b[w8 * S + t];                                      \
            }                                                                  \
            bc_a[t] = sg;                                                      \
            bc_b[t] = sv2;                                                     \
        }                                                                      \
        __syncthreads();                                                       \
        _Pragma("unroll") for (int s = 0; s < S; s++) {                        \
            g[s] = 0.5f * bc_b[s] * g[s] - bc_a[s] * vt[s];                    \
        }                                                                      \
    } while (0)

    for (int step = 0; step < NSTEP; step++) {
        // ---- stage 1: a1 = acc(x, v)
#pragma unroll
        for (int s = 0; s < S; s++) {
            xt_sm[t * S + s] = x[s];
            vt[s] = v[s];
        }
        ACCEL();
#pragma unroll
        for (int s = 0; s < S; s++) { xacc[s] = v[s]; vacc[s] = g[s]; }

        // ---- stage 2: a2 = acc(x + h/2 v, v + h/2 a1)
#pragma unroll
        for (int s = 0; s < S; s++) {
            xt_sm[t * S + s] = x[s] + 0.5f * hstep * v[s];
            vt[s] = v[s] + 0.5f * hstep * g[s];
        }
        ACCEL();
#pragma unroll
        for (int s = 0; s < S; s++) { xacc[s] += 2.0f * vt[s]; vacc[s] += 2.0f * g[s]; }

        // ---- stage 3: a3 = acc(x + h/2 k2x, v + h/2 a2)   (k2x = current vt)
#pragma unroll
        for (int s = 0; s < S; s++) {
            float k2x = vt[s];
            xt_sm[t * S + s] = x[s] + 0.5f * hstep * k2x;
            vt[s] = v[s] + 0.5f * hstep * g[s];
        }
        ACCEL();
#pragma unroll
        for (int s = 0; s < S; s++) { xacc[s] += 2.0f * vt[s]; vacc[s] += 2.0f * g[s]; }

        // ---- stage 4: a4 = acc(x + h k3x, v + h a3)   (k3x = current vt)
#pragma unroll
        for (int s = 0; s < S; s++) {
            float k3x = vt[s];
            xt_sm[t * S + s] = x[s] + hstep * k3x;
            vt[s] = v[s] + hstep * g[s];
        }
        ACCEL();
#pragma unroll
        for (int s = 0; s < S; s++) {
            xacc[s] += vt[s];
            vacc[s] += g[s];
            x[s] += (hstep / 6.0f) * xacc[s];
            v[s] += (hstep / 6.0f) * vacc[s];
        }

        // ---- distance to z_e, track min
#pragma unroll
        for (int s = 0; s < S; s++) {
            float dd = x[s] - Z[(size_t)(NB + s0 + s) * DD + t];
            float p = dd * dd;
#pragma unroll
            for (int off = 16; off > 0; off >>= 1)
                p += __shfl_xor_sync(0xffffffffu, p, off);
            if (lane == 0) red_a[warp * S + s] = p;
        }
        __syncthreads();
        if (t < S) {
            float tot = 0.f;
#pragma unroll
            for (int w8 = 0; w8 < 8; w8++) tot += red_a[w8 * S + t];
            mymin = fminf(mymin, tot);
        }
        __syncthreads();
    }

    if (t < S) mind[s0 + t] = mymin;
#undef ACCEL
#undef MATVEC
}

// ---------------------------------------------------------------------------
// Deterministic final reduction: out = mean(mind) * WEIGHT
// ---------------------------------------------------------------------------
__global__ void reduce_kernel(const float* __restrict__ mind, float* __restrict__ out) {
    __shared__ float sm[1024];
    const int t = threadIdx.x;
    float a = mind[t] + mind[t + 1024] + mind[t + 2048] + mind[t + 3072];
    sm[t] = a;
    __syncthreads();
    for (int off = 512; off > 0; off >>= 1) {
        if (t < off) sm[t] += sm[t + off];
        __syncthreads();
    }
    if (t == 0) out[0] = sm[0] * (1.0f / (float)NB);
}

// ---------------------------------------------------------------------------
// Launch
// ---------------------------------------------------------------------------
extern "C" void kernel_launch(void* const* d_in, const int* in_sizes, int n_in,
                              void* d_out, int out_size) {
    const float* x_start = (const float*)d_in[0];
    const float* x_end   = (const float*)d_in[1];
    const float* noise   = (const float*)d_in[2];
    const float* W1  = (const float*)d_in[3];
    const float* b1  = (const float*)d_in[4];
    const float* W2  = (const float*)d_in[5];
    const float* b2  = (const float*)d_in[6];
    const float* Ww1 = (const float*)d_in[7];
    const float* bw1 = (const float*)d_in[8];
    const float* Ww2 = (const float*)d_in[9];
    const float* bw2 = (const float*)d_in[10];
    const float* Wp1 = (const float*)d_in[11];
    const float* bp1 = (const float*)d_in[12];
    const float* wp2 = (const float*)d_in[13];

    float *Hb, *Zb, *HWb, *Vb, *WpT, *Md;
    cudaGetSymbolAddress((void**)&Hb,  g_H);
    cudaGetSymbolAddress((void**)&Zb,  g_Z);
    cudaGetSymbolAddress((void**)&HWb, g_HW);
    cudaGetSymbolAddress((void**)&Vb,  g_V);
    cudaGetSymbolAddress((void**)&WpT, g_WpT);
    cudaGetSymbolAddress((void**)&Md,  g_mind);

    // Wp1 transpose for the backward matvec
    transpose256<<<DD, DD>>>(Wp1, WpT);

    // Encoder layer 1: H = tanh(X @ W1 + b1)   (start, end)
    sgemm_kernel<1><<<dim3(HH / 128, NB / 128), 256>>>(x_start, W1, b1, Hb, NB, HH, DIN);
    sgemm_kernel<1><<<dim3(HH / 128, NB / 128), 256>>>(x_end,   W1, b1, Hb + (size_t)NB * HH, NB, HH, DIN);
    // Encoder layer 2: Z = H @ W2 + b2   (both halves at once)
    sgemm_kernel<0><<<dim3(DD / 128, 2 * NB / 128), 256>>>(Hb, W2, b2, Zb, 2 * NB, DD, HH);
    // Wind field on z_s
    sgemm_kernel<1><<<dim3(DD / 128, NB / 128), 256>>>(Zb,  Ww1, bw1, HWb, NB, DD, DD);
    sgemm_kernel<0><<<dim3(DD / 128, NB / 128), 256>>>(HWb, Ww2, bw2, Vb,  NB, DD, DD);
    // Degenerate-wind fallback
    fallback_kernel<<<NB, DD>>>(Vb, noise);
    // RK4 geodesic trace + per-sample min distance
    trace_kernel<<<NB / S, DD>>>(Zb, Vb, Wp1, WpT, bp1, wp2, Md);
    // Mean
    reduce_kernel<<<1, 1024>>>(Md, (float*)d_out);
}